// round 3
// baseline (speedup 1.0000x reference)
#include <cuda_runtime.h>

// ---------------------------------------------------------------------------
// Sparse 125-tap equivariant convolution, N=200000 points in 192^3 grid.
// Factored kernel form per tap p:
//   out_s[c]      = sum_i fs[i]*W1'[i][c] + sum_i q[i]*W4'[i][c]
//   out_v[k*3+n]  = v3[n]*(sum_i fs[i]*W2'[i][k]) + sum_i fV[i][n]*W3'[i][k]
// with q[i] = sum_m fV[i][m]*v3[m],
//   W1' = ALPHA*w1, W2' = ALPHA*w2, W3' = ALPHA*w3, W4' = (ALPHA/sqrt3)*w4
//   w = (EMB[p] @ weight)/125, v3 = sqrt(3)*unit(offset)
// ---------------------------------------------------------------------------

#define GRIDL 192
#define NVOX  (192*192*192)
#define NTAP  125
#define TILE  256
#define CHUNK 32

__device__ float g_emb[NTAP * 8];
__device__ float g_v3[NTAP * 3];
__device__ float g_W[NTAP * 2304];
__device__ int   g_vol[NVOX];

// ---- prep 1: radial embedding + spherical vector per tap -------------------
__global__ void k_prep1() {
    int p = threadIdx.x;
    if (p >= NTAP) return;
    float dx = (float)(p / 25) - 2.f;
    float dy = (float)((p / 5) % 5) - 2.f;
    float dz = (float)(p % 5) - 2.f;
    float d = sqrtf(dx * dx + dy * dy + dz * dz);
    const float step = 2.5f / 9.f;
    for (int r = 0; r < 8; r++) {
        float c = step * (float)(r + 1);
        float t = (d - c) / step;
        float e = 0.f;
        if (fabsf(t) < 1.f) {
            float s = 1.f - t * t;
            e = 1.14136f * expf(2.f) * expf(-2.f / s);
        }
        g_emb[p * 8 + r] = e;
    }
    float inv = (d > 0.f) ? (1.f / fmaxf(d, 1e-9f)) : 0.f;
    const float s3 = 1.7320508075688772f;
    g_v3[p * 3 + 0] = s3 * dx * inv;
    g_v3[p * 3 + 1] = s3 * dy * inv;
    g_v3[p * 3 + 2] = s3 * dz * inv;
}

// ---- prep 2: factored, pre-scaled weights ---------------------------------
__global__ void k_prep2(const float* __restrict__ weight) {
    int p = blockIdx.x;
    __shared__ float e[8];
    if (threadIdx.x < 8) e[threadIdx.x] = g_emb[p * 8 + threadIdx.x];
    __syncthreads();
    const float ALPHA = 0.14433756729740643f;      // 1/sqrt(48)
    const float INV125 = 1.f / 125.f;
    const float INVS3 = 0.5773502691896258f;       // 1/sqrt(3)
    for (int c = threadIdx.x; c < 2304; c += blockDim.x) {
        float s = 0.f;
        #pragma unroll
        for (int r = 0; r < 8; r++) s += e[r] * weight[r * 2304 + c];
        s *= INV125;
        float sc = (c < 1792) ? ALPHA : ALPHA * INVS3;
        g_W[p * 2304 + c] = s * sc;
    }
}

// ---- clear voxel volume to -1 ---------------------------------------------
__global__ void k_zero() {
    int i = blockIdx.x * blockDim.x + threadIdx.x;
    int4 m1 = make_int4(-1, -1, -1, -1);
    if (i < NVOX / 4) ((int4*)g_vol)[i] = m1;
}

// ---- scatter point indices ------------------------------------------------
__global__ void k_scatter(const int* __restrict__ coords, int n) {
    int i = blockIdx.x * blockDim.x + threadIdx.x;
    if (i < n) {
        int x = coords[3 * i], y = coords[3 * i + 1], z = coords[3 * i + 2];
        g_vol[(x * GRIDL + y) * GRIDL + z] = i;
    }
}

// ---- main: self-term + 125-tap sparse conv, tiled over 256 points ---------
__global__ void __launch_bounds__(256, 2)
k_main(const float* __restrict__ feats,
       const float* __restrict__ wsc0,
       const float* __restrict__ wsc1,
       const int* __restrict__ coords,
       float* __restrict__ out, int n)
{
    extern __shared__ float sm[];
    float* acc = sm;                          // TILE * 81 (pad to 81 vs bank conflicts)
    float* wsm = acc + TILE * 81;             // 2304
    float* fst = wsm + 2304;                  // CHUNK * 96 (80 feats + 16 q)
    float* w0s = fst + CHUNK * 96;            // 1024
    float* w1s = w0s + 1024;                  // 256
    int*   list = (int*)(w1s + 256);          // TILE
    int*   nhp  = list + TILE;                // 1

    const int tid = threadIdx.x;
    const int pt0 = blockIdx.x * TILE;
    const int mypt = pt0 + tid;
    const bool valid = (mypt < n);
    int cx = 0, cy = 0, cz = 0;
    if (valid) {
        cx = coords[3 * mypt];
        cy = coords[3 * mypt + 1];
        cz = coords[3 * mypt + 2];
    }

    // stage self-interaction weights (pre-scaled)
    for (int i = tid; i < 1024; i += 256) w0s[i] = wsc0[i] * 0.17677669529663687f; // 1/sqrt(32)
    w1s[tid & 255] = wsc1[tid & 255] * 0.25f;                                      // 1/sqrt(16)
    __syncthreads();

    // ---- self (sc) term: thread handles its own point, all 80 channels ----
    if (valid) {
        const float* f = feats + (size_t)mypt * 80;
        float fr[48];
        #pragma unroll
        for (int i = 0; i < 32; i++) fr[i] = f[i];
        #pragma unroll
        for (int c = 0; c < 32; c++) {
            float s = 0.f;
            #pragma unroll
            for (int i = 0; i < 32; i++) s += fr[i] * w0s[i * 32 + c];
            acc[tid * 81 + c] = s;
        }
        #pragma unroll
        for (int i = 0; i < 48; i++) fr[i] = f[32 + i];
        #pragma unroll
        for (int k = 0; k < 16; k++) {
            float s0 = 0.f, s1 = 0.f, s2 = 0.f;
            #pragma unroll
            for (int i = 0; i < 16; i++) {
                float w = w1s[i * 16 + k];
                s0 += fr[i * 3 + 0] * w;
                s1 += fr[i * 3 + 1] * w;
                s2 += fr[i * 3 + 2] * w;
            }
            acc[tid * 81 + 32 + k * 3 + 0] = s0;
            acc[tid * 81 + 32 + k * 3 + 1] = s1;
            acc[tid * 81 + 32 + k * 3 + 2] = s2;
        }
    }

    const int wid = tid >> 5, lane = tid & 31;
    const int kA = lane / 3, nA = lane - kA * 3;
    const int vB = lane + 32;
    const int kBr = vB / 3, nB = vB - kBr * 3;
    const int kB = (lane < 16) ? kBr : 0;     // clamp to keep smem reads in-bounds

    // ---- tap loop ----
    for (int p = 0; p < NTAP; p++) {
        __syncthreads();
        // stage factored weights for this tap
        {
            const float4* wg = (const float4*)(g_W + p * 2304);
            float4* wd = (float4*)wsm;
            for (int i = tid; i < 576; i += 256) wd[i] = wg[i];
        }
        if (tid == 0) *nhp = 0;
        __syncthreads();

        // probe
        int dx = p / 25 - 2, dy = (p / 5) % 5 - 2, dz = p % 5 - 2;
        if (valid) {
            int x = cx + dx, y = cy + dy, z = cz + dz;
            if ((unsigned)x < (unsigned)GRIDL && (unsigned)y < (unsigned)GRIDL &&
                (unsigned)z < (unsigned)GRIDL) {
                int nb = g_vol[(x * GRIDL + y) * GRIDL + z];
                if (nb >= 0) {
                    int pos = atomicAdd(nhp, 1);
                    list[pos] = (tid << 18) | nb;
                }
            }
        }
        __syncthreads();
        const int nh = *nhp;
        const float v30 = g_v3[p * 3], v31 = g_v3[p * 3 + 1], v32 = g_v3[p * 3 + 2];
        const float vA = (nA == 0) ? v30 : ((nA == 1) ? v31 : v32);
        const float vBn = (nB == 0) ? v30 : ((nB == 1) ? v31 : v32);

        for (int base = 0; base < nh; base += CHUNK) {
            int cn = min(CHUNK, nh - base);
            // stage neighbor feats
            for (int idx = tid; idx < cn * 80; idx += 256) {
                int h = idx / 80, k = idx - h * 80;
                int nb = list[base + h] & 0x3FFFF;
                fst[h * 96 + k] = feats[(size_t)nb * 80 + k];
            }
            __syncthreads();
            // q[i] = sum_m V[i][m] * v3[m]
            for (int idx = tid; idx < cn * 16; idx += 256) {
                int h = idx >> 4, i = idx & 15;
                float* fh = fst + h * 96;
                fh[80 + i] = fh[32 + 3 * i] * v30 + fh[33 + 3 * i] * v31 + fh[34 + 3 * i] * v32;
            }
            __syncthreads();
            // process: one warp per hit; lane owns channels {l, 32+l, 64+l(<16)}
            for (int h = wid; h < cn; h += 8) {
                const float* fh = fst + h * 96;
                int packed = list[base + h];
                float* ap = acc + (packed >> 18) * 81;
                float a0 = 0.f, sA = 0.f, sB = 0.f, aA = 0.f, aB = 0.f;
                #pragma unroll
                for (int i = 0; i < 32; i++) {
                    float fi = fh[i];
                    a0 += fi * wsm[i * 32 + lane];
                    sA += fi * wsm[1024 + i * 16 + kA];
                    sB += fi * wsm[1024 + i * 16 + kB];
                }
                #pragma unroll
                for (int i = 0; i < 16; i++) {
                    float qi = fh[80 + i];
                    a0 += qi * wsm[1792 + i * 32 + lane];
                    aA += fh[32 + 3 * i + nA] * wsm[1536 + i * 16 + kA];
                    aB += fh[32 + 3 * i + nB] * wsm[1536 + i * 16 + kB];
                }
                ap[lane] += a0;
                ap[32 + lane] += vA * sA + aA;
                if (lane < 16) ap[64 + lane] += vBn * sB + aB;
            }
            __syncthreads();
        }
    }
    __syncthreads();

    // ---- write out ----
    for (int idx = tid; idx < TILE * 80; idx += 256) {
        int pt = idx / 80, c = idx - pt * 80;
        if (pt0 + pt < n) out[(size_t)(pt0 + pt) * 80 + c] = acc[pt * 81 + c];
    }
}

// ---------------------------------------------------------------------------
extern "C" void kernel_launch(void* const* d_in, const int* in_sizes, int n_in,
                              void* d_out, int out_size) {
    const float* feats  = (const float*)d_in[0];
    const float* weight = (const float*)d_in[1];
    const float* wsc0   = (const float*)d_in[2];
    const float* wsc1   = (const float*)d_in[3];
    const int*   coords = (const int*)d_in[4];
    float* out = (float*)d_out;
    int n = in_sizes[0] / 80;

    static int smem_set = -1;
    const int SMEM = (TILE * 81 + 2304 + CHUNK * 96 + 1024 + 256) * 4 + (TILE + 1) * 4;
    if (smem_set < 0) {
        cudaFuncSetAttribute(k_main, cudaFuncAttributeMaxDynamicSharedMemorySize, SMEM);
        smem_set = 1;
    }

    k_prep1<<<1, 128>>>();
    k_prep2<<<NTAP, 256>>>(weight);
    k_zero<<<(NVOX / 4 + 255) / 256, 256>>>();
    k_scatter<<<(n + 255) / 256, 256>>>(coords, n);

    int nblk = (n + TILE - 1) / TILE;
    k_main<<<nblk, 256, SMEM>>>(feats, wsc0, wsc1, coords, out, n);
}